// round 12
// baseline (speedup 1.0000x reference)
#include <cuda_runtime.h>
#include <math.h>

#define NB 32
#define NA 8400
#define NG 100
#define BA (NB*NA)
#define NBLK3 (33*32)

// ---- device scratch (static globals; zero-initialized at load) ----
__device__ int    g_cnt[BA];
__device__ float  g_miou[BA];
__device__ int    g_nfg[NB];        // reset by k3 last block
__device__ int    g_cidx[BA];
__device__ float4 g_cbox[BA];       // compacted pred bbox CORNERS x0,y0,x1,y1
__device__ float4 g_cgeo[BA];       // xc, yc, r, clsc
__device__ float  g_psum[NBLK3];
__device__ int    g_pcnt[NBLK3];
__device__ int    g_done;

#define LN2X3 2.0794415416798357f   // 3*ln(2)
#define FULLM 0xffffffffu

__device__ __forceinline__ float softplus(float x){
    return fmaxf(x, 0.0f) + log1pf(expf(-fabsf(x)));
}

// ---------------------------------------------------------------------------
// Kernel 1: fg mask + compaction, per-block GT y-culling. Corners stored.
// ---------------------------------------------------------------------------
__global__ void k1_fg_compact(const float* __restrict__ outputs,
                              const float* __restrict__ labels,
                              const float* __restrict__ xs,
                              const float* __restrict__ ys,
                              const float* __restrict__ st){
    __shared__ float4 cgt[NG];
    __shared__ float2 ccen[NG];
    __shared__ int    scv;
    __shared__ float  rmn[8], rmx[8], rrm[8];
    __shared__ float  bymin, bymax, brmax;
    __shared__ int    wcnt[8], wbase[8], blkbase;

    int b = blockIdx.y;
    int a = blockIdx.x*blockDim.x + threadIdx.x;
    bool valid = (a < NA);
    float xc=0.f, yc=0.f, r=0.f;
    if (valid){
        float s  = st[a];
        xc = (xs[a] + 0.5f) * s;
        yc = (ys[a] + 0.5f) * s;
        r  = 2.5f * s;
    }

    int wid = threadIdx.x >> 5, lane = threadIdx.x & 31;
    {
        float mn = valid ? yc :  1e30f;
        float mx = valid ? yc : -1e30f;
        float rm = valid ? r  :  0.0f;
        #pragma unroll
        for (int off = 16; off; off >>= 1){
            mn = fminf(mn, __shfl_down_sync(FULLM, mn, off));
            mx = fmaxf(mx, __shfl_down_sync(FULLM, mx, off));
            rm = fmaxf(rm, __shfl_down_sync(FULLM, rm, off));
        }
        if (lane == 0){ rmn[wid] = mn; rmx[wid] = mx; rrm[wid] = rm; }
    }
    if (threadIdx.x == 0) scv = 0;
    __syncthreads();
    if (threadIdx.x == 0){
        float mn = rmn[0], mx = rmx[0], rm = rrm[0];
        #pragma unroll
        for (int i = 1; i < 8; i++){
            mn = fminf(mn, rmn[i]); mx = fmaxf(mx, rmx[i]); rm = fmaxf(rm, rrm[i]);
        }
        bymin = mn; bymax = mx; brmax = rm;
    }
    __syncthreads();
    float ymin = bymin, ymax = bymax, rmaxb = brmax;

    if (threadIdx.x < NG){
        const float* L = labels + (size_t)(b*NG + threadIdx.x)*5;
        float l0=L[0], gcx=L[1], gcy=L[2], gw=L[3], gh=L[4];
        if ((l0+gcx+gcy+gw+gh) > 0.0f){
            float y0 = gcy - gh*0.5f, y1 = gcy + gh*0.5f;
            bool boxy = (ymax > y0) && (ymin < y1);
            bool ctry = (ymax > gcy - rmaxb) && (ymin < gcy + rmaxb);
            if (boxy || ctry){
                int p = atomicAdd(&scv, 1);
                cgt[p]  = make_float4(gcx - gw*0.5f, y0, gcx + gw*0.5f, y1);
                ccen[p] = make_float2(gcx, gcy);
            }
        }
    }
    __syncthreads();
    int cv = scv;

    bool fg = false;
    if (valid){
        for (int g = 0; g < cv; g++){
            float4 bx = cgt[g];
            float2 cn = ccen[g];
            bool ib = (xc > bx.x) && (xc < bx.z) && (yc > bx.y) && (yc < bx.w);
            bool ic = (fabsf(xc - cn.x) < r) && (fabsf(yc - cn.y) < r);
            if (ib || ic){ fg = true; break; }
        }
        g_cnt[b*NA + a] = 0;
    }

    unsigned ball = __ballot_sync(FULLM, fg);
    if (lane == 0) wcnt[wid] = __popc(ball);
    __syncthreads();
    if (threadIdx.x == 0){
        int tot = 0;
        #pragma unroll
        for (int i = 0; i < 8; i++){ wbase[i] = tot; tot += wcnt[i]; }
        blkbase = tot ? atomicAdd(&g_nfg[b], tot) : 0;
    }
    __syncthreads();

    if (fg){
        int idx = b*NA + a;
        const float* o = outputs + (size_t)idx*6;
        float2 c2 = *(const float2*)(o);
        float2 w2 = *(const float2*)(o + 2);
        float2 oc = *(const float2*)(o + 4);
        float sig_o = __fdividef(1.0f, 1.0f + __expf(-oc.x));
        float sig_c = __fdividef(1.0f, 1.0f + __expf(-oc.y));
        float clsc = -__logf(sqrtf(sig_c * sig_o) + 1e-9f);
        int pos = b*NA + blkbase + wbase[wid] + __popc(ball & ((1u << lane) - 1u));
        g_cidx[pos] = a;
        g_cbox[pos] = make_float4(c2.x - w2.x*0.5f, c2.y - w2.y*0.5f,
                                  c2.x + w2.x*0.5f, c2.y + w2.y*0.5f);
        g_cgeo[pos] = make_float4(xc, yc, r, clsc);
    }
}

// ---------------------------------------------------------------------------
// Kernel 2: 2 warps/GT (even/odd 128-candidate blocks), software-pipelined
// double-buffered loads, exact warp-distributed top-10, smem half-merge.
// ---------------------------------------------------------------------------
__global__ void __launch_bounds__(256) k2_assign(const float* __restrict__ outputs,
                                                 const float* __restrict__ labels){
    __shared__ float scst[4][20];
    __shared__ int   sidw[4][20];
    __shared__ float siou[4][20];

    int b     = blockIdx.y;
    int wid   = threadIdx.x >> 5;
    int lane  = threadIdx.x & 31;
    int gslot = wid >> 1;            // 0..3
    int half  = wid & 1;             // 0..1
    int g     = blockIdx.x*4 + gslot;   // grid.x=25 -> g in [0,100)

    const float* L = labels + (size_t)(b*NG + g)*5;
    float l0=L[0], gcx=L[1], gcy=L[2], gw=L[3], gh=L[4];
    bool validgt = ((l0+gcx+gcy+gw+gh) > 0.0f);

    float gl = gcx - gw*0.5f, gr_ = gcx + gw*0.5f;
    float gt_ = gcy - gh*0.5f, gb = gcy + gh*0.5f;
    float garea = gw*gh;

    int nfg = g_nfg[b];
    const int*    cidx = g_cidx + b*NA;
    const float4* cbox = g_cbox + b*NA;
    const float4* cgeo = g_cgeo + b*NA;

    // distributed lists: lane k<10 holds the global k-th item
    float dc = 3e38f; int di = 0x7fffffff;   // cost asc, lex-(cost,idx)
    float du = 0.0f;                          // iou desc

    auto loadblk = [&](int ibk, float4* BB, float4* GE, int* AV, bool* ACT){
        int base = ibk*128 + lane;
        #pragma unroll
        for (int u = 0; u < 4; u++){
            int j = base + u*32;
            ACT[u] = (j < nfg);
            if (ACT[u]){ BB[u]=cbox[j]; GE[u]=cgeo[j]; AV[u]=cidx[j]; }
            else AV[u] = 0x7fffffff;
        }
    };

    auto procslot = [&](bool act, float4 bb, float4 ge, int a){
        float iou = 0.0f, cost = 3e38f;
        if (act){
            float tlx = fmaxf(gl,  bb.x);
            float tly = fmaxf(gt_, bb.y);
            float brx = fminf(gr_, bb.z);
            float bry = fminf(gb,  bb.w);
            float iw = fmaxf(brx - tlx, 0.0f);
            float ih = fmaxf(bry - tly, 0.0f);
            float inter = iw*ih;
            float barea = (bb.z - bb.x)*(bb.w - bb.y);
            iou = __fdividef(inter, garea + barea - inter + 1e-12f);
            bool ib = (ge.x > gl) && (ge.x < gr_) && (ge.y > gt_) && (ge.y < gb);
            bool ic = (fabsf(ge.x - gcx) < ge.z) && (fabsf(ge.y - gcy) < ge.z);
            cost = ge.w - LN2X3*__log2f(iou + 1e-8f) + ((ib && ic) ? 0.0f : 100000.0f);
        }
        float thrC = __shfl_sync(FULLM, dc, 9);
        int   ti9  = __shfl_sync(FULLM, di, 9);
        float thrI = __shfl_sync(FULLM, du, 9);
        bool doC = act && (cost < thrC || (cost == thrC && a < ti9));
        bool doI = act && (iou > thrI);
        unsigned mC = __ballot_sync(FULLM, doC);
        unsigned mI = __ballot_sync(FULLM, doI);
        while (mC){
            int src = __ffs(mC) - 1; mC &= mC - 1;
            float c = __shfl_sync(FULLM, cost, src);
            int   i = __shfl_sync(FULLM, a,    src);
            bool less = (c < dc) || (c == dc && i < di);
            unsigned m = __ballot_sync(FULLM, less);
            int first = __ffs(m) - 1;
            float pdc = __shfl_up_sync(FULLM, dc, 1);
            int   pdi = __shfl_up_sync(FULLM, di, 1);
            if (less){
                dc = (lane == first) ? c : pdc;
                di = (lane == first) ? i : pdi;
            }
        }
        while (mI){
            int src = __ffs(mI) - 1; mI &= mI - 1;
            float c = __shfl_sync(FULLM, iou, src);
            bool more = (c > du);
            unsigned m = __ballot_sync(FULLM, more);
            int first = __ffs(m) - 1;
            float pdu = __shfl_up_sync(FULLM, du, 1);
            if (more){
                du = (lane == first) ? c : pdu;
            }
        }
    };

    if (validgt){
        int nblk = (nfg + 127) >> 7;
        float4 bbA[4], geA[4]; int avA[4]; bool acA[4];
        float4 bbB[4], geB[4]; int avB[4]; bool acB[4];
        int ibk = half;                     // even/odd blocks per half
        if (ibk < nblk) loadblk(ibk, bbA, geA, avA, acA);
        for (; ibk < nblk; ibk += 2){
            int nx = ibk + 2;
            if (nx < nblk) loadblk(nx, bbB, geB, avB, acB);   // prefetch (MLP)
            #pragma unroll
            for (int u = 0; u < 4; u++) procslot(acA[u], bbA[u], geA[u], avA[u]);
            #pragma unroll
            for (int u = 0; u < 4; u++){ bbA[u]=bbB[u]; geA[u]=geB[u]; avA[u]=avB[u]; acA[u]=acB[u]; }
        }
        if (lane < 10){
            scst[gslot][half*10 + lane] = dc;
            sidw[gslot][half*10 + lane] = di;
            siou[gslot][half*10 + lane] = du;
        }
    }
    __syncthreads();

    if (validgt && half == 0){
        // merge half-1's sorted 10-lists via the same insertion machinery
        float c1 = (lane < 10) ? scst[gslot][10 + lane] : 3e38f;
        int   i1 = (lane < 10) ? sidw[gslot][10 + lane] : 0x7fffffff;
        float u1 = (lane < 10) ? siou[gslot][10 + lane] : 0.0f;

        float thrC = __shfl_sync(FULLM, dc, 9);
        int   ti9  = __shfl_sync(FULLM, di, 9);
        float thrI = __shfl_sync(FULLM, du, 9);
        bool doC = (lane < 10) && (c1 < thrC || (c1 == thrC && i1 < ti9));
        bool doI = (lane < 10) && (u1 > thrI);
        unsigned mC = __ballot_sync(FULLM, doC);
        unsigned mI = __ballot_sync(FULLM, doI);
        while (mC){
            int src = __ffs(mC) - 1; mC &= mC - 1;
            float c = __shfl_sync(FULLM, c1, src);
            int   i = __shfl_sync(FULLM, i1, src);
            bool less = (c < dc) || (c == dc && i < di);
            unsigned m = __ballot_sync(FULLM, less);
            int first = __ffs(m) - 1;
            float pdc = __shfl_up_sync(FULLM, dc, 1);
            int   pdi = __shfl_up_sync(FULLM, di, 1);
            if (less){
                dc = (lane == first) ? c : pdc;
                di = (lane == first) ? i : pdi;
            }
        }
        while (mI){
            int src = __ffs(mI) - 1; mI &= mI - 1;
            float c = __shfl_sync(FULLM, u1, src);
            bool more = (c > du);
            unsigned m = __ballot_sync(FULLM, more);
            int first = __ffs(m) - 1;
            float pdu = __shfl_up_sync(FULLM, du, 1);
            if (more){
                du = (lane == first) ? c : pdu;
            }
        }

        // dyn_k: descending-order sequential sum of merged top-10 ious
        float su = 0.0f;
        #pragma unroll
        for (int k = 0; k < 10; k++) su += __shfl_sync(FULLM, du, k);
        int dynk = (int)su;
        if (dynk < 1) dynk = 1;

        // winners = lanes 0..dynk-1 of merged cost list; parallel scatter
        if (lane < dynk && dc < 1e9f){
            atomicAdd(&g_cnt[b*NA + di], 1);
            const float* o = outputs + (size_t)(b*NA + di)*6;
            float bcx=o[0], bcy=o[1], bw2=o[2]*0.5f, bh2=o[3]*0.5f;
            float tlx = fmaxf(gl,  bcx-bw2), tly = fmaxf(gt_, bcy-bh2);
            float brx = fminf(gr_, bcx+bw2), bry = fminf(gb,  bcy+bh2);
            float iw = fmaxf(brx-tlx, 0.f), ih = fmaxf(bry-tly, 0.f);
            float inter = iw*ih;
            float iou = __fdividef(inter, garea + 4.f*bw2*bh2 - inter + 1e-12f);
            g_miou[b*NA + di] = iou;   // raced only when cnt>1 (then unused)
        }
    }
}

// ---------------------------------------------------------------------------
// Kernel 3: loss over compacted fg + fused last-block final reduce.
// ---------------------------------------------------------------------------
__global__ void k3_loss(const float* __restrict__ outputs,
                        const float* __restrict__ labels,
                        float* __restrict__ out){
    __shared__ float4 sgt[NG];
    __shared__ float2 scen[NG];
    __shared__ float  sarea[NG];
    __shared__ int    snv;
    __shared__ float  ssum[256];
    __shared__ int    scnt[256];
    __shared__ bool   isLast;

    int b = blockIdx.y;
    if (threadIdx.x == 0) snv = 0;
    __syncthreads();
    if (threadIdx.x < NG){
        const float* L = labels + (size_t)(b*NG + threadIdx.x)*5;
        float l0=L[0], gcx=L[1], gcy=L[2], gw=L[3], gh=L[4];
        if ((l0+gcx+gcy+gw+gh) > 0.0f){
            int p = atomicAdd(&snv, 1);
            sgt[p]   = make_float4(gcx - gw*0.5f, gcy - gh*0.5f,
                                   gcx + gw*0.5f, gcy + gh*0.5f);
            scen[p]  = make_float2(gcx, gcy);
            sarea[p] = gw*gh;
        }
    }
    __syncthreads();
    int nv = snv;

    int nfg = g_nfg[b];
    int j = blockIdx.x*blockDim.x + threadIdx.x;
    float term = 0.0f;
    int   isfg = 0;
    if (j < nfg){
        int a   = g_cidx[b*NA + j];
        int cnt = g_cnt[b*NA + a];
        if (cnt >= 1){
            isfg = 1;
            float pred_iou;
            if (cnt == 1){
                pred_iou = g_miou[b*NA + a];
            } else {
                float4 bb = g_cbox[b*NA + j];   // corners
                float4 ge = g_cgeo[b*NA + j];
                float barea = (bb.z - bb.x)*(bb.w - bb.y);
                float bestc = 3e38f, besti = 0.0f;
                for (int g = 0; g < nv; g++){
                    float4 bx = sgt[g];
                    float2 cn = scen[g];
                    float tlx = fmaxf(bx.x, bb.x);
                    float tly = fmaxf(bx.y, bb.y);
                    float brx = fminf(bx.z, bb.z);
                    float bry = fminf(bx.w, bb.w);
                    float iw = fmaxf(brx - tlx, 0.0f);
                    float ih = fmaxf(bry - tly, 0.0f);
                    float inter = iw*ih;
                    float iou = __fdividef(inter, sarea[g] + barea - inter + 1e-12f);
                    bool ib = (ge.x > bx.x) && (ge.x < bx.z) &&
                              (ge.y > bx.y) && (ge.y < bx.w);
                    bool ic = (fabsf(ge.x - cn.x) < ge.z) && (fabsf(ge.y - cn.y) < ge.z);
                    float cost = ge.w - LN2X3*__log2f(iou + 1e-8f) +
                                 ((ib && ic) ? 0.0f : 100000.0f);
                    if (cost < bestc){ bestc = cost; besti = iou; }
                }
                pred_iou = besti;
            }
            float x = outputs[(size_t)(b*NA + a)*6 + 5];
            float sp_p = softplus(x);
            float sp_n = softplus(-x);
            term = pred_iou*sp_n + (1.0f - pred_iou)*sp_p;
        }
    }
    ssum[threadIdx.x] = term;
    scnt[threadIdx.x] = isfg;
    __syncthreads();
    for (int o = 128; o; o >>= 1){
        if (threadIdx.x < o){
            ssum[threadIdx.x] += ssum[threadIdx.x + o];
            scnt[threadIdx.x] += scnt[threadIdx.x + o];
        }
        __syncthreads();
    }
    if (threadIdx.x == 0){
        int blk = blockIdx.y*gridDim.x + blockIdx.x;
        g_psum[blk] = ssum[0];
        g_pcnt[blk] = scnt[0];
        __threadfence();
        int t = atomicAdd(&g_done, 1);
        isLast = (t == NBLK3 - 1);
    }
    __syncthreads();

    if (isLast){
        float s = 0.0f; int c = 0;
        for (int i = threadIdx.x; i < NBLK3; i += 256){ s += g_psum[i]; c += g_pcnt[i]; }
        ssum[threadIdx.x] = s; scnt[threadIdx.x] = c;
        __syncthreads();
        for (int o = 128; o; o >>= 1){
            if (threadIdx.x < o){
                ssum[threadIdx.x] += ssum[threadIdx.x+o];
                scnt[threadIdx.x] += scnt[threadIdx.x+o];
            }
            __syncthreads();
        }
        if (threadIdx.x == 0){
            float nf = (float)scnt[0];
            if (nf < 1.0f) nf = 1.0f;
            out[0] = ssum[0] / nf;
            g_done = 0;
        }
        if (threadIdx.x < NB) g_nfg[threadIdx.x] = 0;
    }
}

extern "C" void kernel_launch(void* const* d_in, const int* in_sizes, int n_in,
                              void* d_out, int out_size){
    const float* outputs = (const float*)d_in[0];  // [32, 8400, 6]
    const float* labels  = (const float*)d_in[1];  // [32, 100, 5]
    const float* xs      = (const float*)d_in[2];  // [1, 8400]
    const float* ys      = (const float*)d_in[3];  // [1, 8400]
    const float* st      = (const float*)d_in[4];  // [1, 8400]

    dim3 ganchor(33, NB);
    k1_fg_compact<<<ganchor, 256>>>(outputs, labels, xs, ys, st);
    k2_assign<<<dim3(25, NB), 256>>>(outputs, labels);
    k3_loss<<<ganchor, 256>>>(outputs, labels, (float*)d_out);
}

// round 13
// speedup vs baseline: 1.3267x; 1.3267x over previous
#include <cuda_runtime.h>
#include <math.h>

#define NB 32
#define NA 8400
#define NG 100
#define BA (NB*NA)
#define NBLK3 (33*32)

// ---- device scratch (static globals; zero-initialized at load) ----
__device__ int    g_cnt[BA];
__device__ float  g_miou[BA];
__device__ int    g_nfg[NB];        // reset by k3 last block
__device__ int    g_cidx[BA];
__device__ float4 g_cbox[BA];       // compacted pred bbox CORNERS x0,y0,x1,y1
__device__ float4 g_cgeo[BA];       // xc, yc, r, clsc
__device__ float  g_psum[NBLK3];
__device__ int    g_pcnt[NBLK3];
__device__ int    g_done;

#define LN2X3 2.0794415416798357f   // 3*ln(2)
#define FULLM 0xffffffffu

__device__ __forceinline__ float softplus(float x){
    return fmaxf(x, 0.0f) + log1pf(expf(-fabsf(x)));
}

// ---------------------------------------------------------------------------
// Kernel 1: fg mask + compaction, per-block GT y-culling. Corners stored.
// ---------------------------------------------------------------------------
__global__ void k1_fg_compact(const float* __restrict__ outputs,
                              const float* __restrict__ labels,
                              const float* __restrict__ xs,
                              const float* __restrict__ ys,
                              const float* __restrict__ st){
    __shared__ float4 cgt[NG];
    __shared__ float2 ccen[NG];
    __shared__ int    scv;
    __shared__ float  rmn[8], rmx[8], rrm[8];
    __shared__ float  bymin, bymax, brmax;
    __shared__ int    wcnt[8], wbase[8], blkbase;

    int b = blockIdx.y;
    int a = blockIdx.x*blockDim.x + threadIdx.x;
    bool valid = (a < NA);
    float xc=0.f, yc=0.f, r=0.f;
    if (valid){
        float s  = st[a];
        xc = (xs[a] + 0.5f) * s;
        yc = (ys[a] + 0.5f) * s;
        r  = 2.5f * s;
    }

    int wid = threadIdx.x >> 5, lane = threadIdx.x & 31;
    {
        float mn = valid ? yc :  1e30f;
        float mx = valid ? yc : -1e30f;
        float rm = valid ? r  :  0.0f;
        #pragma unroll
        for (int off = 16; off; off >>= 1){
            mn = fminf(mn, __shfl_down_sync(FULLM, mn, off));
            mx = fmaxf(mx, __shfl_down_sync(FULLM, mx, off));
            rm = fmaxf(rm, __shfl_down_sync(FULLM, rm, off));
        }
        if (lane == 0){ rmn[wid] = mn; rmx[wid] = mx; rrm[wid] = rm; }
    }
    if (threadIdx.x == 0) scv = 0;
    __syncthreads();
    if (threadIdx.x == 0){
        float mn = rmn[0], mx = rmx[0], rm = rrm[0];
        #pragma unroll
        for (int i = 1; i < 8; i++){
            mn = fminf(mn, rmn[i]); mx = fmaxf(mx, rmx[i]); rm = fmaxf(rm, rrm[i]);
        }
        bymin = mn; bymax = mx; brmax = rm;
    }
    __syncthreads();
    float ymin = bymin, ymax = bymax, rmaxb = brmax;

    if (threadIdx.x < NG){
        const float* L = labels + (size_t)(b*NG + threadIdx.x)*5;
        float l0=L[0], gcx=L[1], gcy=L[2], gw=L[3], gh=L[4];
        if ((l0+gcx+gcy+gw+gh) > 0.0f){
            float y0 = gcy - gh*0.5f, y1 = gcy + gh*0.5f;
            bool boxy = (ymax > y0) && (ymin < y1);
            bool ctry = (ymax > gcy - rmaxb) && (ymin < gcy + rmaxb);
            if (boxy || ctry){
                int p = atomicAdd(&scv, 1);
                cgt[p]  = make_float4(gcx - gw*0.5f, y0, gcx + gw*0.5f, y1);
                ccen[p] = make_float2(gcx, gcy);
            }
        }
    }
    __syncthreads();
    int cv = scv;

    bool fg = false;
    if (valid){
        for (int g = 0; g < cv; g++){
            float4 bx = cgt[g];
            float2 cn = ccen[g];
            bool ib = (xc > bx.x) && (xc < bx.z) && (yc > bx.y) && (yc < bx.w);
            bool ic = (fabsf(xc - cn.x) < r) && (fabsf(yc - cn.y) < r);
            if (ib || ic){ fg = true; break; }
        }
        g_cnt[b*NA + a] = 0;
    }

    unsigned ball = __ballot_sync(FULLM, fg);
    if (lane == 0) wcnt[wid] = __popc(ball);
    __syncthreads();
    if (threadIdx.x == 0){
        int tot = 0;
        #pragma unroll
        for (int i = 0; i < 8; i++){ wbase[i] = tot; tot += wcnt[i]; }
        blkbase = tot ? atomicAdd(&g_nfg[b], tot) : 0;
    }
    __syncthreads();

    if (fg){
        int idx = b*NA + a;
        const float* o = outputs + (size_t)idx*6;
        float2 c2 = *(const float2*)(o);
        float2 w2 = *(const float2*)(o + 2);
        float2 oc = *(const float2*)(o + 4);
        float sig_o = __fdividef(1.0f, 1.0f + __expf(-oc.x));
        float sig_c = __fdividef(1.0f, 1.0f + __expf(-oc.y));
        float clsc = -__logf(sqrtf(sig_c * sig_o) + 1e-9f);
        int pos = b*NA + blkbase + wbase[wid] + __popc(ball & ((1u << lane) - 1u));
        g_cidx[pos] = a;
        g_cbox[pos] = make_float4(c2.x - w2.x*0.5f, c2.y - w2.y*0.5f,
                                  c2.x + w2.x*0.5f, c2.y + w2.y*0.5f);
        g_cgeo[pos] = make_float4(xc, yc, r, clsc);
    }
}

// ---------------------------------------------------------------------------
// Kernel 2: 1 warp/GT; MLP=4 batched loads; exact warp-distributed top-10
// with CACHED thresholds + single-ballot fast path.
// ---------------------------------------------------------------------------
__global__ void k2_assign(const float* __restrict__ outputs,
                          const float* __restrict__ labels){
    int b    = blockIdx.y;
    int wid  = threadIdx.x >> 5;
    int lane = threadIdx.x & 31;
    int g    = blockIdx.x*8 + wid;
    if (g >= NG) return;

    const float* L = labels + (size_t)(b*NG + g)*5;
    float l0=L[0], gcx=L[1], gcy=L[2], gw=L[3], gh=L[4];
    if (!((l0+gcx+gcy+gw+gh) > 0.0f)) return;

    float gl = gcx - gw*0.5f, gr_ = gcx + gw*0.5f;
    float gt_ = gcy - gh*0.5f, gb = gcy + gh*0.5f;
    float garea = gw*gh;

    int nfg = g_nfg[b];
    const int*    cidx = g_cidx + b*NA;
    const float4* cbox = g_cbox + b*NA;
    const float4* cgeo = g_cgeo + b*NA;

    // distributed lists: lane k<10 holds the global k-th item
    float dc = 3e38f; int di = 0x7fffffff;   // cost asc, lex-(cost,idx)
    float du = 0.0f;                          // iou desc

    // cached broadcast thresholds (== list 10th; refreshed after mutations)
    float thrC = 3e38f; int ti9 = 0x7fffffff; float thrI = 0.0f;

    int nblk = (nfg + 127) >> 7;
    for (int ibk = 0; ibk < nblk; ibk++){
        int base = ibk*128 + lane;

        // batched loads (MLP=4)
        float4 bbv[4], gev[4]; int av[4]; bool actv[4];
        #pragma unroll
        for (int u = 0; u < 4; u++){
            int j = base + u*32;
            actv[u] = (j < nfg);
            if (actv[u]){
                bbv[u] = cbox[j];
                gev[u] = cgeo[j];
                av[u]  = cidx[j];
            } else av[u] = 0x7fffffff;
        }

        #pragma unroll
        for (int u = 0; u < 4; u++){
            bool act = actv[u];
            float iou = 0.0f, cost = 3e38f;
            int a = av[u];
            if (act){
                float4 bb = bbv[u];
                float4 ge = gev[u];
                float tlx = fmaxf(gl,  bb.x);
                float tly = fmaxf(gt_, bb.y);
                float brx = fminf(gr_, bb.z);
                float bry = fminf(gb,  bb.w);
                float iw = fmaxf(brx - tlx, 0.0f);
                float ih = fmaxf(bry - tly, 0.0f);
                float inter = iw*ih;
                float barea = (bb.z - bb.x)*(bb.w - bb.y);
                iou = __fdividef(inter, garea + barea - inter + 1e-12f);
                bool ib = (ge.x > gl) && (ge.x < gr_) && (ge.y > gt_) && (ge.y < gb);
                bool ic = (fabsf(ge.x - gcx) < ge.z) && (fabsf(ge.y - gcy) < ge.z);
                cost = ge.w - LN2X3*__log2f(iou + 1e-8f) + ((ib && ic) ? 0.0f : 100000.0f);
            }

            // admission test against CACHED thresholds (no shfl on fast path)
            bool doC = act && (cost < thrC || (cost == thrC && a < ti9));
            bool doI = act && (iou > thrI);
            unsigned many = __ballot_sync(FULLM, doC || doI);
            if (many){
                unsigned mC = __ballot_sync(FULLM, doC);
                unsigned mI = __ballot_sync(FULLM, doI);
                while (mC){
                    int src = __ffs(mC) - 1; mC &= mC - 1;
                    float c = __shfl_sync(FULLM, cost, src);
                    int   i = __shfl_sync(FULLM, a,    src);
                    bool less = (c < dc) || (c == dc && i < di);
                    unsigned m = __ballot_sync(FULLM, less);
                    int first = __ffs(m) - 1;
                    float pdc = __shfl_up_sync(FULLM, dc, 1);
                    int   pdi = __shfl_up_sync(FULLM, di, 1);
                    if (less){
                        dc = (lane == first) ? c : pdc;
                        di = (lane == first) ? i : pdi;
                    }
                }
                while (mI){
                    int src = __ffs(mI) - 1; mI &= mI - 1;
                    float c = __shfl_sync(FULLM, iou, src);
                    bool more = (c > du);
                    unsigned m = __ballot_sync(FULLM, more);
                    int first = __ffs(m) - 1;
                    float pdu = __shfl_up_sync(FULLM, du, 1);
                    if (more){
                        du = (lane == first) ? c : pdu;
                    }
                }
                // refresh cached thresholds (only after mutations)
                thrC = __shfl_sync(FULLM, dc, 9);
                ti9  = __shfl_sync(FULLM, di, 9);
                thrI = __shfl_sync(FULLM, du, 9);
            }
        }
    }

    // dyn_k: descending-order sequential sum of top-10 ious (matches reference)
    float su = 0.0f;
    #pragma unroll
    for (int k = 0; k < 10; k++) su += __shfl_sync(FULLM, du, k);
    int dynk = (int)su;
    if (dynk < 1) dynk = 1;

    // winners are lanes 0..dynk-1 of the cost list; scatter in parallel
    if (lane < dynk && dc < 1e9f){
        atomicAdd(&g_cnt[b*NA + di], 1);
        const float* o = outputs + (size_t)(b*NA + di)*6;
        float bcx=o[0], bcy=o[1], bw2=o[2]*0.5f, bh2=o[3]*0.5f;
        float tlx = fmaxf(gl,  bcx-bw2), tly = fmaxf(gt_, bcy-bh2);
        float brx = fminf(gr_, bcx+bw2), bry = fminf(gb,  bcy+bh2);
        float iw = fmaxf(brx-tlx, 0.f), ih = fmaxf(bry-tly, 0.f);
        float inter = iw*ih;
        float iou = __fdividef(inter, garea + 4.f*bw2*bh2 - inter + 1e-12f);
        g_miou[b*NA + di] = iou;   // raced only when cnt>1 (then unused)
    }
}

// ---------------------------------------------------------------------------
// Kernel 3: loss over compacted fg + fused last-block final reduce.
// ---------------------------------------------------------------------------
__global__ void k3_loss(const float* __restrict__ outputs,
                        const float* __restrict__ labels,
                        float* __restrict__ out){
    __shared__ float4 sgt[NG];
    __shared__ float2 scen[NG];
    __shared__ float  sarea[NG];
    __shared__ int    snv;
    __shared__ float  ssum[256];
    __shared__ int    scnt[256];
    __shared__ bool   isLast;

    int b = blockIdx.y;
    if (threadIdx.x == 0) snv = 0;
    __syncthreads();
    if (threadIdx.x < NG){
        const float* L = labels + (size_t)(b*NG + threadIdx.x)*5;
        float l0=L[0], gcx=L[1], gcy=L[2], gw=L[3], gh=L[4];
        if ((l0+gcx+gcy+gw+gh) > 0.0f){
            int p = atomicAdd(&snv, 1);
            sgt[p]   = make_float4(gcx - gw*0.5f, gcy - gh*0.5f,
                                   gcx + gw*0.5f, gcy + gh*0.5f);
            scen[p]  = make_float2(gcx, gcy);
            sarea[p] = gw*gh;
        }
    }
    __syncthreads();
    int nv = snv;

    int nfg = g_nfg[b];
    int j = blockIdx.x*blockDim.x + threadIdx.x;
    float term = 0.0f;
    int   isfg = 0;
    if (j < nfg){
        int a   = g_cidx[b*NA + j];
        int cnt = g_cnt[b*NA + a];
        if (cnt >= 1){
            isfg = 1;
            float pred_iou;
            if (cnt == 1){
                pred_iou = g_miou[b*NA + a];
            } else {
                float4 bb = g_cbox[b*NA + j];   // corners
                float4 ge = g_cgeo[b*NA + j];
                float barea = (bb.z - bb.x)*(bb.w - bb.y);
                float bestc = 3e38f, besti = 0.0f;
                for (int g = 0; g < nv; g++){
                    float4 bx = sgt[g];
                    float2 cn = scen[g];
                    float tlx = fmaxf(bx.x, bb.x);
                    float tly = fmaxf(bx.y, bb.y);
                    float brx = fminf(bx.z, bb.z);
                    float bry = fminf(bx.w, bb.w);
                    float iw = fmaxf(brx - tlx, 0.0f);
                    float ih = fmaxf(bry - tly, 0.0f);
                    float inter = iw*ih;
                    float iou = __fdividef(inter, sarea[g] + barea - inter + 1e-12f);
                    bool ib = (ge.x > bx.x) && (ge.x < bx.z) &&
                              (ge.y > bx.y) && (ge.y < bx.w);
                    bool ic = (fabsf(ge.x - cn.x) < ge.z) && (fabsf(ge.y - cn.y) < ge.z);
                    float cost = ge.w - LN2X3*__log2f(iou + 1e-8f) +
                                 ((ib && ic) ? 0.0f : 100000.0f);
                    if (cost < bestc){ bestc = cost; besti = iou; }
                }
                pred_iou = besti;
            }
            float x = outputs[(size_t)(b*NA + a)*6 + 5];
            float sp_p = softplus(x);
            float sp_n = softplus(-x);
            term = pred_iou*sp_n + (1.0f - pred_iou)*sp_p;
        }
    }
    ssum[threadIdx.x] = term;
    scnt[threadIdx.x] = isfg;
    __syncthreads();
    for (int o = 128; o; o >>= 1){
        if (threadIdx.x < o){
            ssum[threadIdx.x] += ssum[threadIdx.x + o];
            scnt[threadIdx.x] += scnt[threadIdx.x + o];
        }
        __syncthreads();
    }
    if (threadIdx.x == 0){
        int blk = blockIdx.y*gridDim.x + blockIdx.x;
        g_psum[blk] = ssum[0];
        g_pcnt[blk] = scnt[0];
        __threadfence();
        int t = atomicAdd(&g_done, 1);
        isLast = (t == NBLK3 - 1);
    }
    __syncthreads();

    if (isLast){
        float s = 0.0f; int c = 0;
        for (int i = threadIdx.x; i < NBLK3; i += 256){ s += g_psum[i]; c += g_pcnt[i]; }
        ssum[threadIdx.x] = s; scnt[threadIdx.x] = c;
        __syncthreads();
        for (int o = 128; o; o >>= 1){
            if (threadIdx.x < o){
                ssum[threadIdx.x] += ssum[threadIdx.x+o];
                scnt[threadIdx.x] += scnt[threadIdx.x+o];
            }
            __syncthreads();
        }
        if (threadIdx.x == 0){
            float nf = (float)scnt[0];
            if (nf < 1.0f) nf = 1.0f;
            out[0] = ssum[0] / nf;
            g_done = 0;
        }
        if (threadIdx.x < NB) g_nfg[threadIdx.x] = 0;
    }
}

extern "C" void kernel_launch(void* const* d_in, const int* in_sizes, int n_in,
                              void* d_out, int out_size){
    const float* outputs = (const float*)d_in[0];  // [32, 8400, 6]
    const float* labels  = (const float*)d_in[1];  // [32, 100, 5]
    const float* xs      = (const float*)d_in[2];  // [1, 8400]
    const float* ys      = (const float*)d_in[3];  // [1, 8400]
    const float* st      = (const float*)d_in[4];  // [1, 8400]

    dim3 ganchor(33, NB);
    k1_fg_compact<<<ganchor, 256>>>(outputs, labels, xs, ys, st);
    k2_assign<<<dim3(13, NB), 256>>>(outputs, labels);
    k3_loss<<<ganchor, 256>>>(outputs, labels, (float*)d_out);
}